// round 1
// baseline (speedup 1.0000x reference)
#include <cuda_runtime.h>
#include <cstdint>

// Problem constants
#define BB   512
#define SS   1024
#define INW  32
#define HH   128
#define GG   512          // 4*H
#define RR   4            // batch rows per CTA
#define NBLK 128          // 512 / RR
#define NTHR 512
#define WSTRIDE 100       // 96 weight floats + 4 pad (breaks 32-bank alignment)

#define W_SH_FLOATS (GG * WSTRIDE)                       // 51200
#define H_SH_FLOATS (RR * HH)                            // 512
#define X_SH_FLOATS (RR * INW)                           // 128
#define G_SH_FLOATS (RR * GG)                            // 2048
#define SMEM_FLOATS (W_SH_FLOATS + H_SH_FLOATS + X_SH_FLOATS + G_SH_FLOATS)
#define SMEM_BYTES  (SMEM_FLOATS * 4)                    // 215552 B < 227 KiB cap

// Packed fp32x2 FMA (Blackwell only; ptxas never emits it from C++)
__device__ __forceinline__ unsigned long long ffma2(unsigned long long a,
                                                    unsigned long long b,
                                                    unsigned long long c) {
    unsigned long long d;
    asm("fma.rn.f32x2 %0, %1, %2, %3;" : "=l"(d) : "l"(a), "l"(b), "l"(c));
    return d;
}

__device__ __forceinline__ void unpack2(unsigned long long v, float& lo, float& hi) {
    asm("mov.b64 {%0, %1}, %2;" : "=f"(lo), "=f"(hi) : "l"(v));
}

__device__ __forceinline__ float sigmoid_f(float v) {
    return __fdividef(1.0f, 1.0f + __expf(-v));
}
__device__ __forceinline__ float tanh_f(float v) {
    // 1 - 2/(e^{2v}+1); saturates correctly for |v| large (expf -> inf/0)
    return 1.0f - __fdividef(2.0f, __expf(2.0f * v) + 1.0f);
}

__global__ void __launch_bounds__(NTHR, 1)
lstm_fused_kernel(const float* __restrict__ x,     // [B,S,IN]
                  const float* __restrict__ Wih,   // [4H,IN]
                  const float* __restrict__ Whh,   // [4H,H]
                  const float* __restrict__ bih,   // [4H]
                  const float* __restrict__ bhh,   // [4H]
                  const float* __restrict__ Wlin,  // [1, S*H]
                  const float* __restrict__ blin,  // [1]
                  float* __restrict__ out)         // [B,1]
{
    extern __shared__ float sm[];
    float* w_sh = sm;                              // [512][WSTRIDE]: cols 0..63 = Whh[g][64..127], 64..95 = Wih[g][0..31]
    float* h_sh = sm + W_SH_FLOATS;                // [RR][128]
    float* x_sh = h_sh + H_SH_FLOATS;              // [RR][32]
    float* gbuf = x_sh + X_SH_FLOATS;              // [RR][512]

    const int tid = threadIdx.x;
    const int g   = tid;                           // gate row owned by this thread
    const int b0  = blockIdx.x * RR;

    // ---- Prologue: weights into registers + smem ----
    unsigned long long wr[32];                     // Whh[g][0:64] as 32 packed fp32 pairs
    {
        const unsigned long long* wrow =
            reinterpret_cast<const unsigned long long*>(Whh + (size_t)g * HH);
        #pragma unroll
        for (int i = 0; i < 32; i++) wr[i] = wrow[i];
    }
    const float bias = bih[g] + bhh[g];

    for (int idx = tid; idx < GG * 96; idx += NTHR) {
        int gg = idx / 96, i = idx % 96;
        float v = (i < 64) ? Whh[(size_t)gg * HH + 64 + i]
                           : Wih[(size_t)gg * INW + (i - 64)];
        w_sh[gg * WSTRIDE + i] = v;
    }
    if (tid < H_SH_FLOATS) h_sh[tid] = 0.0f;
    if (tid < RR * INW) {
        int rr = tid >> 5, ii = tid & 31;
        x_sh[tid] = x[(size_t)(b0 + rr) * SS * INW + ii];   // t = 0
    }

    // elementwise role: thread handles hidden component j of row r_ew
    const int j    = tid & (HH - 1);
    const int r_ew = tid >> 7;
    float c_state = 0.0f;
    float lin_acc = 0.0f;

    __syncthreads();

    // ---- Main sequential loop over timesteps ----
    #pragma unroll 1
    for (int t = 0; t < SS; t++) {
        // === Gate phase: thread g computes gate preact for its 4 batch rows ===
        unsigned long long acc[RR];
        #pragma unroll
        for (int r = 0; r < RR; r++) acc[r] = 0ull;

        // recurrent, register-resident half: k = 0..63
        #pragma unroll
        for (int q = 0; q < 16; q++) {
            #pragma unroll
            for (int r = 0; r < RR; r++) {
                ulonglong2 h4 = *reinterpret_cast<const ulonglong2*>(h_sh + r * HH + 4 * q);
                acc[r] = ffma2(wr[2 * q],     h4.x, acc[r]);
                acc[r] = ffma2(wr[2 * q + 1], h4.y, acc[r]);
            }
        }
        // recurrent, smem half: k = 64..127
        const ulonglong2* wp = reinterpret_cast<const ulonglong2*>(w_sh + g * WSTRIDE);
        #pragma unroll
        for (int q = 0; q < 16; q++) {
            ulonglong2 w4 = wp[q];
            #pragma unroll
            for (int r = 0; r < RR; r++) {
                ulonglong2 h4 = *reinterpret_cast<const ulonglong2*>(h_sh + r * HH + 64 + 4 * q);
                acc[r] = ffma2(w4.x, h4.x, acc[r]);
                acc[r] = ffma2(w4.y, h4.y, acc[r]);
            }
        }
        // input projection: Wih in w_sh cols 64..95 (= pair index 16..23)
        #pragma unroll
        for (int q = 0; q < 8; q++) {
            ulonglong2 w4 = wp[16 + q];
            #pragma unroll
            for (int r = 0; r < RR; r++) {
                ulonglong2 h4 = *reinterpret_cast<const ulonglong2*>(x_sh + r * INW + 4 * q);
                acc[r] = ffma2(w4.x, h4.x, acc[r]);
                acc[r] = ffma2(w4.y, h4.y, acc[r]);
            }
        }
        #pragma unroll
        for (int r = 0; r < RR; r++) {
            float lo, hi;
            unpack2(acc[r], lo, hi);
            gbuf[r * GG + g] = lo + hi + bias;
        }
        __syncthreads();

        // === Elementwise phase ===
        {
            float ig = gbuf[r_ew * GG + j];
            float fg = gbuf[r_ew * GG + HH + j];
            float gg = gbuf[r_ew * GG + 2 * HH + j];
            float og = gbuf[r_ew * GG + 3 * HH + j];
            float iv = sigmoid_f(ig);
            float fv = sigmoid_f(fg);
            float gv = tanh_f(gg);
            float ov = sigmoid_f(og);
            c_state = fmaf(fv, c_state, iv * gv);
            float hv = ov * tanh_f(c_state);
            h_sh[r_ew * HH + j] = hv;
            lin_acc = fmaf(hv, __ldg(Wlin + (size_t)t * HH + j), lin_acc);
        }
        // prefetch x for t+1 (overlaps elementwise latency)
        if (t + 1 < SS && tid < RR * INW) {
            int rr = tid >> 5, ii = tid & 31;
            x_sh[tid] = x[(size_t)(b0 + rr) * SS * INW + (size_t)(t + 1) * INW + ii];
        }
        __syncthreads();
    }

    // ---- Epilogue: reduce fused-linear accumulators (128 threads per row) ----
    float v = lin_acc;
    #pragma unroll
    for (int off = 16; off; off >>= 1) v += __shfl_xor_sync(0xffffffffu, v, off);
    if ((tid & 31) == 0) gbuf[tid >> 5] = v;      // 16 warp partials; warps 4r..4r+3 belong to row r
    __syncthreads();
    if (tid < RR) {
        float s = gbuf[4 * tid] + gbuf[4 * tid + 1] + gbuf[4 * tid + 2] + gbuf[4 * tid + 3];
        out[b0 + tid] = s + blin[0];
    }
}

extern "C" void kernel_launch(void* const* d_in, const int* in_sizes, int n_in,
                              void* d_out, int out_size)
{
    const float* x    = (const float*)d_in[0];
    const float* Wih  = (const float*)d_in[1];
    const float* Whh  = (const float*)d_in[2];
    const float* bih  = (const float*)d_in[3];
    const float* bhh  = (const float*)d_in[4];
    const float* Wlin = (const float*)d_in[5];
    const float* blin = (const float*)d_in[6];
    float* out = (float*)d_out;

    cudaFuncSetAttribute(lstm_fused_kernel,
                         cudaFuncAttributeMaxDynamicSharedMemorySize, SMEM_BYTES);
    lstm_fused_kernel<<<NBLK, NTHR, SMEM_BYTES>>>(x, Wih, Whh, bih, bhh, Wlin, blin, out);
}

// round 2
// speedup vs baseline: 1.4788x; 1.4788x over previous
#include <cuda_runtime.h>
#include <cstdint>

// Problem constants
#define BB   512
#define SS   1024
#define INW  32
#define HH   128
#define GG   512          // 4*H
#define RR   4            // batch rows per CTA
#define NBLK 128          // 512 / RR
#define NTHR 256          // each thread: 2 gates x 4 rows
#define WREG 80           // weight floats per gate kept in registers (k = 0..79)
#define WSM  80           // per gate in smem: Whh[80:128) = 48 floats + Wih 32 floats
#define WSTRIDE 84        // 80 + 4 pad; 84 mod 32 = 20, gcd(20,32)=4 -> conflict-free LDS.128

#define W_SH_FLOATS (GG * WSTRIDE)                       // 43008
#define H_SH_FLOATS (RR * HH)                            // 512
#define X_SH_FLOATS (RR * INW)                           // 128
#define G_SH_FLOATS (RR * GG)                            // 2048
#define SMEM_FLOATS (W_SH_FLOATS + H_SH_FLOATS + X_SH_FLOATS + G_SH_FLOATS)
#define SMEM_BYTES  (SMEM_FLOATS * 4)                    // 182784 B < 227 KiB cap

// Packed fp32x2 FMA (Blackwell; ptxas never emits it from C++)
__device__ __forceinline__ unsigned long long ffma2(unsigned long long a,
                                                    unsigned long long b,
                                                    unsigned long long c) {
    unsigned long long d;
    asm("fma.rn.f32x2 %0, %1, %2, %3;" : "=l"(d) : "l"(a), "l"(b), "l"(c));
    return d;
}

__device__ __forceinline__ void unpack2(unsigned long long v, float& lo, float& hi) {
    asm("mov.b64 {%0, %1}, %2;" : "=f"(lo), "=f"(hi) : "l"(v));
}

__device__ __forceinline__ float sigmoid_f(float v) {
    return __fdividef(1.0f, 1.0f + __expf(-v));
}
__device__ __forceinline__ float tanh_f(float v) {
    // 1 - 2/(e^{2v}+1); saturates correctly for |v| large (expf -> inf/0)
    return 1.0f - __fdividef(2.0f, __expf(2.0f * v) + 1.0f);
}

__global__ void __launch_bounds__(NTHR, 1)
lstm_fused_kernel(const float* __restrict__ x,     // [B,S,IN]
                  const float* __restrict__ Wih,   // [4H,IN]
                  const float* __restrict__ Whh,   // [4H,H]
                  const float* __restrict__ bih,   // [4H]
                  const float* __restrict__ bhh,   // [4H]
                  const float* __restrict__ Wlin,  // [1, S*H]
                  const float* __restrict__ blin,  // [1]
                  float* __restrict__ out)         // [B,1]
{
    extern __shared__ float sm[];
    float* w_sh = sm;                              // [512][WSTRIDE]: 0..47 = Whh[g][80..127], 48..79 = Wih[g][0..31]
    float* h_sh = sm + W_SH_FLOATS;                // [RR][128]
    float* x_sh = h_sh + H_SH_FLOATS;              // [RR][32]
    float* gbuf = x_sh + X_SH_FLOATS;              // [RR][512]

    const int tid = threadIdx.x;
    const int ga  = tid;                           // first gate row
    const int gb  = tid + 256;                     // second gate row
    const int b0  = blockIdx.x * RR;

    // ---- Prologue: weights into registers + smem ----
    unsigned long long wA[40], wB[40];             // Whh[g][0:80) as 40 packed fp32 pairs each
    {
        const ulonglong2* pa = reinterpret_cast<const ulonglong2*>(Whh + (size_t)ga * HH);
        const ulonglong2* pb = reinterpret_cast<const ulonglong2*>(Whh + (size_t)gb * HH);
        #pragma unroll
        for (int i = 0; i < 20; i++) {
            ulonglong2 v = pa[i]; wA[2 * i] = v.x; wA[2 * i + 1] = v.y;
            ulonglong2 w = pb[i]; wB[2 * i] = w.x; wB[2 * i + 1] = w.y;
        }
    }
    const float biasA = bih[ga] + bhh[ga];
    const float biasB = bih[gb] + bhh[gb];

    for (int idx = tid; idx < GG * WSM; idx += NTHR) {
        int gg = idx / WSM, i = idx % WSM;
        float v = (i < 48) ? Whh[(size_t)gg * HH + WREG + i]
                           : Wih[(size_t)gg * INW + (i - 48)];
        w_sh[gg * WSTRIDE + i] = v;
    }
    for (int idx = tid; idx < H_SH_FLOATS; idx += NTHR) h_sh[idx] = 0.0f;
    if (tid < RR * INW) {
        int rr = tid >> 5, ii = tid & 31;
        x_sh[tid] = x[(size_t)(b0 + rr) * SS * INW + ii];   // t = 0
    }

    // elementwise role: thread handles units (r0, j) and (r0+2, j)
    const int j  = tid & (HH - 1);
    const int r0 = tid >> 7;                       // 0 or 1
    float c0 = 0.0f, c1 = 0.0f;
    float lin0 = 0.0f, lin1 = 0.0f;

    __syncthreads();

    const ulonglong2* wpa = reinterpret_cast<const ulonglong2*>(w_sh + ga * WSTRIDE);
    const ulonglong2* wpb = reinterpret_cast<const ulonglong2*>(w_sh + gb * WSTRIDE);

    // ---- Main sequential loop over timesteps ----
    #pragma unroll 1
    for (int t = 0; t < SS; t++) {
        // Early global loads: addresses independent of gate results -> latency
        // fully hidden under the gate GEMM below.
        float wl = __ldg(Wlin + (size_t)t * HH + j);
        float xr = 0.0f;
        if (tid < RR * INW) {
            int rr = tid >> 5, ii = tid & 31;
            int tn = (t + 1 < SS) ? (t + 1) : t;
            xr = x[(size_t)(b0 + rr) * SS * INW + (size_t)tn * INW + ii];
        }

        // === Gate phase: 2 gates x 4 rows per thread ===
        unsigned long long aA[RR], aB[RR];
        #pragma unroll
        for (int r = 0; r < RR; r++) { aA[r] = 0ull; aB[r] = 0ull; }

        // register-resident weights: k = 0..79 (20 quads)
        #pragma unroll
        for (int q = 0; q < 20; q++) {
            #pragma unroll
            for (int r = 0; r < RR; r++) {
                ulonglong2 h4 = *reinterpret_cast<const ulonglong2*>(h_sh + r * HH + 4 * q);
                aA[r] = ffma2(wA[2 * q],     h4.x, aA[r]);
                aA[r] = ffma2(wA[2 * q + 1], h4.y, aA[r]);
                aB[r] = ffma2(wB[2 * q],     h4.x, aB[r]);
                aB[r] = ffma2(wB[2 * q + 1], h4.y, aB[r]);
            }
        }
        // smem weights, recurrent part: k = 80..127 (12 quads)
        #pragma unroll
        for (int q = 0; q < 12; q++) {
            ulonglong2 wa = wpa[q];
            ulonglong2 wb = wpb[q];
            #pragma unroll
            for (int r = 0; r < RR; r++) {
                ulonglong2 h4 = *reinterpret_cast<const ulonglong2*>(h_sh + r * HH + WREG + 4 * q);
                aA[r] = ffma2(wa.x, h4.x, aA[r]);
                aA[r] = ffma2(wa.y, h4.y, aA[r]);
                aB[r] = ffma2(wb.x, h4.x, aB[r]);
                aB[r] = ffma2(wb.y, h4.y, aB[r]);
            }
        }
        // input projection: 8 quads (w_sh pair index 12..19)
        #pragma unroll
        for (int q = 0; q < 8; q++) {
            ulonglong2 wa = wpa[12 + q];
            ulonglong2 wb = wpb[12 + q];
            #pragma unroll
            for (int r = 0; r < RR; r++) {
                ulonglong2 x4 = *reinterpret_cast<const ulonglong2*>(x_sh + r * INW + 4 * q);
                aA[r] = ffma2(wa.x, x4.x, aA[r]);
                aA[r] = ffma2(wa.y, x4.y, aA[r]);
                aB[r] = ffma2(wb.x, x4.x, aB[r]);
                aB[r] = ffma2(wb.y, x4.y, aB[r]);
            }
        }
        #pragma unroll
        for (int r = 0; r < RR; r++) {
            float lo, hi;
            unpack2(aA[r], lo, hi);
            gbuf[r * GG + ga] = lo + hi + biasA;
            unpack2(aB[r], lo, hi);
            gbuf[r * GG + gb] = lo + hi + biasB;
        }
        __syncthreads();

        // === Elementwise phase: 2 hidden units per thread ===
        {
            float ig = gbuf[r0 * GG + j];
            float fg = gbuf[r0 * GG + HH + j];
            float gg = gbuf[r0 * GG + 2 * HH + j];
            float og = gbuf[r0 * GG + 3 * HH + j];
            float iv = sigmoid_f(ig);
            float fv = sigmoid_f(fg);
            float gv = tanh_f(gg);
            float ov = sigmoid_f(og);
            c0 = fmaf(fv, c0, iv * gv);
            float hv = ov * tanh_f(c0);
            h_sh[r0 * HH + j] = hv;
            lin0 = fmaf(hv, wl, lin0);
        }
        {
            int r1 = r0 + 2;
            float ig = gbuf[r1 * GG + j];
            float fg = gbuf[r1 * GG + HH + j];
            float gg = gbuf[r1 * GG + 2 * HH + j];
            float og = gbuf[r1 * GG + 3 * HH + j];
            float iv = sigmoid_f(ig);
            float fv = sigmoid_f(fg);
            float gv = tanh_f(gg);
            float ov = sigmoid_f(og);
            c1 = fmaf(fv, c1, iv * gv);
            float hv = ov * tanh_f(c1);
            h_sh[r1 * HH + j] = hv;
            lin1 = fmaf(hv, wl, lin1);
        }
        // publish prefetched x for t+1 (gate-phase reads of t completed at barrier 1)
        if (tid < RR * INW) x_sh[tid] = xr;
        __syncthreads();
    }

    // ---- Epilogue: reduce fused-linear accumulators ----
    float v0 = lin0, v1 = lin1;
    #pragma unroll
    for (int off = 16; off; off >>= 1) {
        v0 += __shfl_xor_sync(0xffffffffu, v0, off);
        v1 += __shfl_xor_sync(0xffffffffu, v1, off);
    }
    const int wi = tid >> 5;                       // warp id 0..7
    if ((tid & 31) == 0) {
        // warp wi covers rows (wi>>2) [pair0] and 2+(wi>>2) [pair1], j-block wi&3
        gbuf[(wi >> 2) * 4 + (wi & 3)]       = v0;
        gbuf[(2 + (wi >> 2)) * 4 + (wi & 3)] = v1;
    }
    __syncthreads();
    if (tid < RR) {
        float s = gbuf[4 * tid] + gbuf[4 * tid + 1] + gbuf[4 * tid + 2] + gbuf[4 * tid + 3];
        out[b0 + tid] = s + blin[0];
    }
}

extern "C" void kernel_launch(void* const* d_in, const int* in_sizes, int n_in,
                              void* d_out, int out_size)
{
    const float* x    = (const float*)d_in[0];
    const float* Wih  = (const float*)d_in[1];
    const float* Whh  = (const float*)d_in[2];
    const float* bih  = (const float*)d_in[3];
    const float* bhh  = (const float*)d_in[4];
    const float* Wlin = (const float*)d_in[5];
    const float* blin = (const float*)d_in[6];
    float* out = (float*)d_out;

    cudaFuncSetAttribute(lstm_fused_kernel,
                         cudaFuncAttributeMaxDynamicSharedMemorySize, SMEM_BYTES);
    lstm_fused_kernel<<<NBLK, NTHR, SMEM_BYTES>>>(x, Wih, Whh, bih, bhh, Wlin, blin, out);
}